// round 1
// baseline (speedup 1.0000x reference)
#include <cuda_runtime.h>
#include <math.h>

#define C 256
#define H 384
#define W 384
#define TILE_H 8
#define TILE_W 32
#define OC_T 16
#define CI_T 4
#define THREADS 128

// Output tile per block: TILE_H x TILE_W spatial x OC_T output channels.
// Each thread: one oc, 2 output rows x 16 output cols (32 accumulators).
// K-loop over input channels in chunks of CI_T, staging input halo tile
// (CI_T x 10 x 34) and weight chunk (CI_T x OC_T x 9) in shared memory.
__global__ __launch_bounds__(THREADS) void masked_conv_kernel(
    const float* __restrict__ x,      // [C, H, W]
    const int*   __restrict__ spa,    // [H, W]
    const float* __restrict__ wgt,    // [C_out, C_in, 3, 3]
    const float* __restrict__ chm,    // [C, 2]
    float* __restrict__ out)          // [C, H, W]
{
    __shared__ float s_in[CI_T][10][34];   // halo tile, stride 34 (bank-friendly)
    __shared__ float s_w[CI_T][OC_T][9];

    const int tid  = threadIdx.x;
    const int w0   = blockIdx.x * TILE_W;
    const int h0   = blockIdx.y * TILE_H;
    const int ocg  = blockIdx.z * OC_T;

    const int oc_l  = tid >> 3;        // 0..15
    const int rem   = tid & 7;
    const int rp    = rem >> 1;        // 0..3 (row pair)
    const int half  = rem & 1;         // 0..1 (column half)
    const int r0    = rp * 2;          // local out rows r0, r0+1
    const int cbase = half * 16;       // local out cols cbase..cbase+15

    float acc[2][16];
    #pragma unroll
    for (int i = 0; i < 2; i++)
        #pragma unroll
        for (int j = 0; j < 16; j++) acc[i][j] = 0.0f;

    for (int ci0 = 0; ci0 < C; ci0 += CI_T) {
        __syncthreads();
        // Stage input halo tile: CI_T x 10 x 34 (zero-padded borders)
        #pragma unroll 4
        for (int i = tid; i < CI_T * 10 * 34; i += THREADS) {
            int ci = i / 340;
            int rr = i - ci * 340;
            int r  = rr / 34;
            int c  = rr - r * 34;
            int gh = h0 + r - 1;
            int gw = w0 + c - 1;
            float v = 0.0f;
            if ((unsigned)gh < (unsigned)H && (unsigned)gw < (unsigned)W)
                v = x[(ci0 + ci) * (H * W) + gh * W + gw];
            s_in[ci][r][c] = v;
        }
        // Stage weights: CI_T x OC_T x 9
        #pragma unroll 2
        for (int i = tid; i < CI_T * OC_T * 9; i += THREADS) {
            int ci = i / (OC_T * 9);
            int rr = i - ci * (OC_T * 9);
            int oc = rr / 9;
            int k  = rr - oc * 9;
            s_w[ci][oc][k] = wgt[((ocg + oc) * C + ci0 + ci) * 9 + k];
        }
        __syncthreads();

        #pragma unroll
        for (int ci = 0; ci < CI_T; ci++) {
            float wv[9];
            #pragma unroll
            for (int k = 0; k < 9; k++) wv[k] = s_w[ci][oc_l][k];

            // 4-row x 3-col register sliding window over 16 output cols
            float win[4][3];
            #pragma unroll
            for (int ir = 0; ir < 4; ir++) {
                win[ir][1] = s_in[ci][r0 + ir][cbase + 0];
                win[ir][2] = s_in[ci][r0 + ir][cbase + 1];
            }
            #pragma unroll
            for (int j = 0; j < 16; j++) {
                #pragma unroll
                for (int ir = 0; ir < 4; ir++) {
                    win[ir][0] = win[ir][1];
                    win[ir][1] = win[ir][2];
                    win[ir][2] = s_in[ci][r0 + ir][cbase + j + 2];
                }
                #pragma unroll
                for (int kh = 0; kh < 3; kh++)
                    #pragma unroll
                    for (int kw = 0; kw < 3; kw++) {
                        acc[0][j] = fmaf(wv[kh * 3 + kw], win[kh    ][kw], acc[0][j]);
                        acc[1][j] = fmaf(wv[kh * 3 + kw], win[kh + 1][kw], acc[1][j]);
                    }
            }
        }
    }

    // Epilogue: channel gate (softmax->round) + spatial mask + ReLU
    const int oc = ocg + oc_l;
    const float a = chm[oc * 2 + 0];
    const float b = chm[oc * 2 + 1];
    // softmax over 2 logits; rintf == round-half-to-even == jnp.round
    const float dflag = rintf(1.0f / (1.0f + expf(b - a)));
    const float sflag = rintf(1.0f / (1.0f + expf(a - b)));

    #pragma unroll
    for (int i = 0; i < 2; i++) {
        const int gh = h0 + r0 + i;
        const long long rowbase = (long long)oc * (H * W) + (long long)gh * W;
        #pragma unroll
        for (int j = 0; j < 16; j++) {
            const int gw = w0 + cbase + j;
            const float g = dflag + sflag * (float)spa[gh * W + gw];
            const float v = acc[i][j] * g;
            out[rowbase + gw] = v > 0.0f ? v : 0.0f;
        }
    }
}

// Second output of the reference tuple: ch_round [1, C, 2]
__global__ void chround_kernel(const float* __restrict__ chm, float* __restrict__ out) {
    int c = blockIdx.x * blockDim.x + threadIdx.x;
    if (c < C) {
        float a = chm[2 * c + 0];
        float b = chm[2 * c + 1];
        out[2 * c + 0] = rintf(1.0f / (1.0f + expf(b - a)));
        out[2 * c + 1] = rintf(1.0f / (1.0f + expf(a - b)));
    }
}

extern "C" void kernel_launch(void* const* d_in, const int* in_sizes, int n_in,
                              void* d_out, int out_size) {
    const float* x   = (const float*)d_in[0];   // x [1,256,384,384] f32
    const int*   spa = (const int*)  d_in[1];   // spa_mask [1,1,384,384] i32
    const float* wgt = (const float*)d_in[2];   // weight [256,256,3,3] f32
    const float* chm = (const float*)d_in[3];   // ch_mask [1,256,2] f32

    float* out = (float*)d_out;

    dim3 grid(W / TILE_W, H / TILE_H, C / OC_T);   // (12, 48, 16)
    masked_conv_kernel<<<grid, THREADS>>>(x, spa, wgt, chm, out);

    // ch_round goes after the conv output if the harness allocated room for it.
    const int conv_elems = C * H * W;
    if (out_size >= conv_elems + 2 * C) {
        chround_kernel<<<1, 256>>>(chm, out + conv_elems);
    }
}

// round 5
// speedup vs baseline: 1.9296x; 1.9296x over previous
#include <cuda_runtime.h>
#include <mma.h>
#include <math.h>
#include <stdint.h>

using namespace nvcuda;

#define CC 256
#define HH 384
#define WW 384
#define HP 386
#define WP 386
#define HW (HH * WW)

// ---------------- scratch (static device arrays; no allocs) ----------------
__device__ __align__(16) float g_x[(size_t)HP * WP * CC];  // padded [h][w][ci], tf32-rounded
__device__ __align__(16) float g_w[9 * CC * CC];           // [tap][oc][ci], tf32-rounded

// ---------------- helpers ----------------
__device__ __forceinline__ float to_tf32(float x) {
    uint32_t y;
    asm("cvt.rna.tf32.f32 %0, %1;" : "=r"(y) : "f"(x));
    return __uint_as_float(y);
}
__device__ __forceinline__ void cp16(float* dst_smem, const float* src) {
    uint32_t d = (uint32_t)__cvta_generic_to_shared(dst_smem);
    asm volatile("cp.async.cg.shared.global [%0], [%1], 16;" :: "r"(d), "l"(src));
}
#define CP_COMMIT() asm volatile("cp.async.commit_group;" ::: "memory")
#define CP_WAIT1()  asm volatile("cp.async.wait_group 1;" ::: "memory")
#define CP_WAIT0()  asm volatile("cp.async.wait_group 0;" ::: "memory")

// ---------------- prep kernels ----------------
__global__ void prep_w_kernel(const float* __restrict__ w) {
    int idx = blockIdx.x * blockDim.x + threadIdx.x;
    if (idx >= 9 * CC * CC) return;
    int ci = idx % CC;
    int rest = idx / CC;
    int oc = rest % CC;
    int t = rest / CC;
    g_w[idx] = to_tf32(w[(oc * CC + ci) * 9 + t]);
}

// transpose [ci][h][w] -> padded [h+1][w+1][ci], tf32-rounded
__global__ void prep_x_kernel(const float* __restrict__ x) {
    __shared__ float tile[32][33];
    int w0 = blockIdx.x * 32;
    int cg = blockIdx.y * 32;
    int h = blockIdx.z;
    int tx = threadIdx.x, ty = threadIdx.y;  // 32 x 8
    #pragma unroll
    for (int i = 0; i < 4; i++)
        tile[ty + 8 * i][tx] = x[(size_t)(cg + ty + 8 * i) * HW + (size_t)h * WW + w0 + tx];
    __syncthreads();
    #pragma unroll
    for (int i = 0; i < 4; i++)
        g_x[((size_t)(h + 1) * WP + (w0 + ty + 8 * i + 1)) * CC + cg + tx] =
            to_tf32(tile[tx][ty + 8 * i]);
}

// zero the 1-pixel border of the padded array
__global__ void zero_border_kernel() {
    int i = blockIdx.x * blockDim.x + threadIdx.x;
    const int rowN = 2 * WP * CC;        // h = 0 and h = 385, all w
    const int colN = 2 * HH * CC;        // w = 0 and w = 385, h = 1..384
    if (i < rowN) {
        int half = i / (WP * CC);
        int rem = i % (WP * CC);
        int h = half ? (HP - 1) : 0;
        g_x[((size_t)h * WP) * CC + rem] = 0.0f;
    } else if (i < rowN + colN) {
        int j = i - rowN;
        int half = j / (HH * CC);
        int rem = j % (HH * CC);
        int h = 1 + rem / CC;
        int ci = rem % CC;
        int w = half ? (WP - 1) : 0;
        g_x[((size_t)h * WP + w) * CC + ci] = 0.0f;
    }
}

// ---------------- main conv kernel ----------------
// grid (6, 192, 2): CTA tile = 128 oc x (2 h-rows x 64 w).  256 threads, 8 warps (4m x 2n).
// smem (floats): A[2] @ 0 / 4608 (128 x 36), B[2] @ 9216 / 18720 (4*66 x 36).  Total 112896 B.
#define A_STRIDE 36
#define B_STRIDE 36
#define A_FLOATS 4608
#define B_FLOATS 9504
#define SMEM_FLOATS 28224
#define SMEM_BYTES (SMEM_FLOATS * 4)

__global__ void __launch_bounds__(256, 2) conv_main(
    const int* __restrict__ spa,
    const float* __restrict__ chm,
    float* __restrict__ out)
{
    extern __shared__ float sm[];
    float* Abuf[2] = {sm, sm + A_FLOATS};
    float* Bbuf[2] = {sm + 2 * A_FLOATS, sm + 2 * A_FLOATS + B_FLOATS};

    const int tid = threadIdx.x;
    const int wid = tid >> 5;
    const int w0 = blockIdx.x * 64;
    const int h0 = blockIdx.y * 2;
    const int oc0 = blockIdx.z * 128;
    const int wm = wid >> 1;   // 0..3  (oc quadrant, 32 rows)
    const int wn = wid & 1;    // 0..1  (h-row half, 64 pixels)

    wmma::fragment<wmma::accumulator, 16, 16, 8, float> acc[2][4];
    #pragma unroll
    for (int m = 0; m < 2; m++)
        #pragma unroll
        for (int n = 0; n < 4; n++) wmma::fill_fragment(acc[m][n], 0.0f);

    auto issueA = [&](int it, int st) {
        const int c = it / 9, t = it % 9;
        const float* base = g_w + ((size_t)t * CC + oc0) * CC + c * 32;
        float* dst = Abuf[st];
        #pragma unroll
        for (int i = tid; i < 1024; i += 256) {
            int row = i >> 3, ch = i & 7;
            cp16(dst + row * A_STRIDE + ch * 4, base + (size_t)row * CC + ch * 4);
        }
    };
    auto issueB = [&](int c, int st) {
        // padded coords: logical h0-1+r -> h0+r ; logical w0-1+wc -> w0+wc
        const float* base = g_x + ((size_t)h0 * WP + w0) * CC + c * 32;
        float* dst = Bbuf[st];
        for (int i = tid; i < 2112; i += 256) {
            int r = i / 528;
            int rem = i - r * 528;
            int wc = rem >> 3, ch = rem & 7;
            cp16(dst + (r * 66 + wc) * B_STRIDE + ch * 4,
                 base + ((size_t)r * WP + wc) * CC + ch * 4);
        }
    };

    issueB(0, 0);
    issueA(0, 0);
    CP_COMMIT();

    for (int it = 0; it < 72; it++) {
        const int c = it / 9, t = it % 9;
        if (it + 1 < 72) {
            issueA(it + 1, (it + 1) & 1);
            if ((it + 1) % 9 == 0) issueB(c + 1, (c + 1) & 1);
        }
        CP_COMMIT();
        CP_WAIT1();
        __syncthreads();

        const float* As = Abuf[it & 1] + wm * 32 * A_STRIDE;
        const float* Bs = Bbuf[c & 1];
        const int kh = t / 3, kw = t % 3;
        #pragma unroll
        for (int ks = 0; ks < 4; ks++) {
            wmma::fragment<wmma::matrix_a, 16, 16, 8, wmma::precision::tf32, wmma::row_major> a0, a1;
            wmma::load_matrix_sync(a0, As + ks * 8, A_STRIDE);
            wmma::load_matrix_sync(a1, As + 16 * A_STRIDE + ks * 8, A_STRIDE);
            #pragma unroll
            for (int n = 0; n < 4; n++) {
                wmma::fragment<wmma::matrix_b, 16, 16, 8, wmma::precision::tf32, wmma::col_major> b;
                const int ws = n * 16;
                wmma::load_matrix_sync(b, Bs + ((wn + kh) * 66 + ws + kw) * B_STRIDE + ks * 8, B_STRIDE);
                wmma::mma_sync(acc[0][n], a0, b, acc[0][n]);
                wmma::mma_sync(acc[1][n], a1, b, acc[1][n]);
            }
        }
        __syncthreads();
    }

    CP_WAIT0();
    __syncthreads();

    // ---- epilogue: acc -> smem -> gate(relu) -> gmem ----
    float* ep = sm + wid * 2176;  // 32 rows x 68
    #pragma unroll
    for (int m = 0; m < 2; m++)
        #pragma unroll
        for (int n = 0; n < 4; n++)
            wmma::store_matrix_sync(ep + m * 16 * 68 + n * 16, acc[m][n], 68, wmma::mem_row_major);
    __syncthreads();

    for (int i = tid; i < 128 * 32; i += 256) {   // float4 granules: 128 oc x 32
        const int ocL = i >> 5;
        const int p = (i & 31) * 4;               // pixel 0..127
        const int row = p >> 6;                   // h-row within tile
        const int wloc = p & 63;
        const int wpr = ((ocL >> 5) << 1) | row;  // source warp region
        const float* src = sm + wpr * 2176 + (ocL & 31) * 68 + wloc;

        const int oc = oc0 + ocL;
        const int h = h0 + row;
        const float av = chm[2 * oc], bv = chm[2 * oc + 1];
        const float dflag = rintf(1.0f / (1.0f + expf(bv - av)));
        const float sflag = rintf(1.0f / (1.0f + expf(av - bv)));

        const int* sp = spa + h * WW + w0 + wloc;
        float4 v;
        float* vp = (float*)&v;
        #pragma unroll
        for (int e = 0; e < 4; e++) {
            const float g = dflag + sflag * (float)sp[e];
            const float val = src[e] * g;
            vp[e] = val > 0.0f ? val : 0.0f;
        }
        *(float4*)(out + (size_t)oc * HW + (size_t)h * WW + w0 + wloc) = v;
    }
}

// ---------------- ch_round tail output ----------------
__global__ void chround_kernel(const float* __restrict__ chm, float* __restrict__ o) {
    int c = blockIdx.x * blockDim.x + threadIdx.x;
    if (c < CC) {
        float a = chm[2 * c + 0];
        float b = chm[2 * c + 1];
        o[2 * c + 0] = rintf(1.0f / (1.0f + expf(b - a)));
        o[2 * c + 1] = rintf(1.0f / (1.0f + expf(a - b)));
    }
}

// ---------------- host ----------------
extern "C" void kernel_launch(void* const* d_in, const int* in_sizes, int n_in,
                              void* d_out, int out_size) {
    const float* x   = (const float*)d_in[0];   // [1,256,384,384] f32
    const int*   spa = (const int*)  d_in[1];   // [1,1,384,384] i32
    const float* wgt = (const float*)d_in[2];   // [256,256,3,3] f32
    const float* chm = (const float*)d_in[3];   // [1,256,2] f32
    float* out = (float*)d_out;

    {
        const int n = 2 * WP * CC + 2 * HH * CC;
        zero_border_kernel<<<(n + 255) / 256, 256>>>();
    }
    prep_w_kernel<<<(9 * CC * CC + 255) / 256, 256>>>(wgt);
    {
        dim3 g(WW / 32, CC / 32, HH), b(32, 8);
        prep_x_kernel<<<g, b>>>(x);
    }

    cudaFuncSetAttribute(conv_main, cudaFuncAttributeMaxDynamicSharedMemorySize, SMEM_BYTES);
    dim3 grid(WW / 64, HH / 2, 2);
    conv_main<<<grid, 256, SMEM_BYTES>>>(spa, chm, out);

    const int conv_elems = CC * HW;
    if (out_size >= conv_elems + 2 * CC) {
        chround_kernel<<<1, 256>>>(chm, out + conv_elems);
    }
}

// round 6
// speedup vs baseline: 7.5083x; 3.8912x over previous
#include <cuda_runtime.h>
#include <cuda_fp16.h>
#include <mma.h>
#include <math.h>
#include <stdint.h>

using namespace nvcuda;

#define CC 256
#define HH 384
#define WW 384
#define HP 386
#define WP 386
#define HW (HH * WW)

// ---------------- scratch (static device arrays; no allocs) ----------------
__device__ __align__(16) __half g_xh[(size_t)HP * WP * CC];  // padded [h][w][ci], fp16
__device__ __align__(16) __half g_wh[9 * CC * CC];           // [tap][oc][ci], fp16

// ---------------- helpers ----------------
__device__ __forceinline__ void cp16(__half* dst_smem, const __half* src) {
    uint32_t d = (uint32_t)__cvta_generic_to_shared(dst_smem);
    asm volatile("cp.async.cg.shared.global [%0], [%1], 16;" :: "r"(d), "l"(src));
}
#define CP_COMMIT() asm volatile("cp.async.commit_group;" ::: "memory")
#define CP_WAIT1()  asm volatile("cp.async.wait_group 1;" ::: "memory")
#define CP_WAIT0()  asm volatile("cp.async.wait_group 0;" ::: "memory")

// ---------------- prep kernels ----------------
__global__ void prep_w_kernel(const float* __restrict__ w) {
    int idx = blockIdx.x * blockDim.x + threadIdx.x;
    if (idx >= 9 * CC * CC) return;
    int ci = idx % CC;
    int rest = idx / CC;
    int oc = rest % CC;
    int t = rest / CC;
    g_wh[idx] = __float2half_rn(w[(oc * CC + ci) * 9 + t]);
}

// transpose [ci][h][w] -> padded [h+1][w+1][ci], fp16
__global__ void prep_x_kernel(const float* __restrict__ x) {
    __shared__ float tile[32][33];
    int w0 = blockIdx.x * 32;
    int cg = blockIdx.y * 32;
    int h = blockIdx.z;
    int tx = threadIdx.x, ty = threadIdx.y;  // 32 x 8
    #pragma unroll
    for (int i = 0; i < 4; i++)
        tile[ty + 8 * i][tx] = x[(size_t)(cg + ty + 8 * i) * HW + (size_t)h * WW + w0 + tx];
    __syncthreads();
    #pragma unroll
    for (int i = 0; i < 4; i++)
        g_xh[((size_t)(h + 1) * WP + (w0 + ty + 8 * i + 1)) * CC + cg + tx] =
            __float2half_rn(tile[tx][ty + 8 * i]);
}

// zero the 1-pixel border of the padded array
__global__ void zero_border_kernel() {
    int i = blockIdx.x * blockDim.x + threadIdx.x;
    const int rowN = 2 * WP * CC;        // h = 0 and h = 385, all w
    const int colN = 2 * HH * CC;        // w = 0 and w = 385, h = 1..384
    if (i < rowN) {
        int half = i / (WP * CC);
        int rem = i % (WP * CC);
        int h = half ? (HP - 1) : 0;
        g_xh[((size_t)h * WP) * CC + rem] = __float2half_rn(0.0f);
    } else if (i < rowN + colN) {
        int j = i - rowN;
        int half = j / (HH * CC);
        int rem = j % (HH * CC);
        int h = 1 + rem / CC;
        int ci = rem % CC;
        int w = half ? (WP - 1) : 0;
        g_xh[((size_t)h * WP + w) * CC + ci] = __float2half_rn(0.0f);
    }
}

// ---------------- main conv kernel ----------------
// grid (6, 192, 2): CTA tile = 128 oc x (2 h-rows x 64 w). 256 threads, 8 warps (4m x 2n).
// K-chunk = 64 ci per stage; 4 ci-chunks x 9 taps = 36 iterations of k=64 (4 x k16).
// smem (halves): A[2] (128 x 72) @ 0 / 9216, B[2] (4*66 x 72) @ 18432 / 37440.
#define A_STRIDE 72
#define B_STRIDE 72
#define A_HALVES 9216            // 128 * 72
#define B_HALVES 19008           // 264 * 72
#define SMEM_HALVES (2 * A_HALVES + 2 * B_HALVES)   // 56448
#define SMEM_BYTES (SMEM_HALVES * 2)                // 112896

__global__ void __launch_bounds__(256, 2) conv_main(
    const int* __restrict__ spa,
    const float* __restrict__ chm,
    float* __restrict__ out)
{
    extern __shared__ __half smh[];
    __half* Abuf[2] = {smh, smh + A_HALVES};
    __half* Bbuf[2] = {smh + 2 * A_HALVES, smh + 2 * A_HALVES + B_HALVES};
    float* smf = (float*)smh;   // epilogue reuse

    const int tid = threadIdx.x;
    const int wid = tid >> 5;
    const int w0 = blockIdx.x * 64;
    const int h0 = blockIdx.y * 2;
    const int oc0 = blockIdx.z * 128;
    const int wm = wid >> 1;   // 0..3  (oc quadrant, 32 rows)
    const int wn = wid & 1;    // 0..1  (h-row half, 64 pixels)

    wmma::fragment<wmma::accumulator, 16, 16, 16, float> acc[2][4];
    #pragma unroll
    for (int m = 0; m < 2; m++)
        #pragma unroll
        for (int n = 0; n < 4; n++) wmma::fill_fragment(acc[m][n], 0.0f);

    // stage = (ci chunk c, tap t): A tile = w[t][oc0..+128][c*64..+64]
    auto issueA = [&](int it, int st) {
        const int c = it / 9, t = it % 9;
        const __half* base = g_wh + ((size_t)t * CC + oc0) * CC + c * 64;
        __half* dst = Abuf[st];
        #pragma unroll
        for (int i = tid; i < 1024; i += 256) {
            int row = i >> 3, ch = i & 7;
            cp16(dst + row * A_STRIDE + ch * 8, base + (size_t)row * CC + ch * 8);
        }
    };
    auto issueB = [&](int c, int st) {
        // padded coords: logical h0-1+r -> padded h0+r ; logical w0-1+wc -> padded w0+wc
        const __half* base = g_xh + ((size_t)h0 * WP + w0) * CC + c * 64;
        __half* dst = Bbuf[st];
        for (int i = tid; i < 2112; i += 256) {
            int r = i / 528;
            int rem = i - r * 528;
            int wc = rem >> 3, ch = rem & 7;
            cp16(dst + (r * 66 + wc) * B_STRIDE + ch * 8,
                 base + ((size_t)r * WP + wc) * CC + ch * 8);
        }
    };

    issueB(0, 0);
    issueA(0, 0);
    CP_COMMIT();

    for (int it = 0; it < 36; it++) {
        const int c = it / 9, t = it % 9;
        if (it + 1 < 36) {
            issueA(it + 1, (it + 1) & 1);
            if ((it + 1) % 9 == 0) issueB(c + 1, (c + 1) & 1);
        }
        CP_COMMIT();
        CP_WAIT1();
        __syncthreads();

        const __half* As = Abuf[it & 1] + wm * 32 * A_STRIDE;
        const __half* Bs = Bbuf[c & 1];
        const int kh = t / 3, kw = t % 3;
        #pragma unroll
        for (int ks = 0; ks < 4; ks++) {
            wmma::fragment<wmma::matrix_a, 16, 16, 16, __half, wmma::row_major> a0, a1;
            wmma::load_matrix_sync(a0, As + ks * 16, A_STRIDE);
            wmma::load_matrix_sync(a1, As + 16 * A_STRIDE + ks * 16, A_STRIDE);
            #pragma unroll
            for (int n = 0; n < 4; n++) {
                wmma::fragment<wmma::matrix_b, 16, 16, 16, __half, wmma::col_major> b;
                const int ws = n * 16;
                wmma::load_matrix_sync(b, Bs + ((wn + kh) * 66 + ws + kw) * B_STRIDE + ks * 16, B_STRIDE);
                wmma::mma_sync(acc[0][n], a0, b, acc[0][n]);
                wmma::mma_sync(acc[1][n], a1, b, acc[1][n]);
            }
        }
        __syncthreads();
    }

    CP_WAIT0();
    __syncthreads();

    // ---- epilogue: acc -> smem -> gate(relu) -> gmem ----
    float* ep = smf + wid * 2176;  // 32 rows x 68
    #pragma unroll
    for (int m = 0; m < 2; m++)
        #pragma unroll
        for (int n = 0; n < 4; n++)
            wmma::store_matrix_sync(ep + m * 16 * 68 + n * 16, acc[m][n], 68, wmma::mem_row_major);
    __syncthreads();

    for (int i = tid; i < 128 * 32; i += 256) {   // float4 granules: 128 oc x 32
        const int ocL = i >> 5;
        const int p = (i & 31) * 4;               // pixel 0..127
        const int row = p >> 6;                   // h-row within tile
        const int wloc = p & 63;
        const int wpr = ((ocL >> 5) << 1) | row;  // source warp region
        const float* src = smf + wpr * 2176 + (ocL & 31) * 68 + wloc;

        const int oc = oc0 + ocL;
        const int h = h0 + row;
        const float av = chm[2 * oc], bv = chm[2 * oc + 1];
        const float dflag = rintf(1.0f / (1.0f + expf(bv - av)));
        const float sflag = rintf(1.0f / (1.0f + expf(av - bv)));

        const int* sp = spa + h * WW + w0 + wloc;
        float4 v;
        float* vp = (float*)&v;
        #pragma unroll
        for (int e = 0; e < 4; e++) {
            const float g = dflag + sflag * (float)sp[e];
            const float val = src[e] * g;
            vp[e] = val > 0.0f ? val : 0.0f;
        }
        *(float4*)(out + (size_t)oc * HW + (size_t)h * WW + w0 + wloc) = v;
    }
}

// ---------------- ch_round tail output ----------------
__global__ void chround_kernel(const float* __restrict__ chm, float* __restrict__ o) {
    int c = blockIdx.x * blockDim.x + threadIdx.x;
    if (c < CC) {
        float a = chm[2 * c + 0];
        float b = chm[2 * c + 1];
        o[2 * c + 0] = rintf(1.0f / (1.0f + expf(b - a)));
        o[2 * c + 1] = rintf(1.0f / (1.0f + expf(a - b)));
    }
}

// ---------------- host ----------------
extern "C" void kernel_launch(void* const* d_in, const int* in_sizes, int n_in,
                              void* d_out, int out_size) {
    const float* x   = (const float*)d_in[0];   // [1,256,384,384] f32
    const int*   spa = (const int*)  d_in[1];   // [1,1,384,384] i32
    const float* wgt = (const float*)d_in[2];   // [256,256,3,3] f32
    const float* chm = (const float*)d_in[3];   // [1,256,2] f32
    float* out = (float*)d_out;

    {
        const int n = 2 * WP * CC + 2 * HH * CC;
        zero_border_kernel<<<(n + 255) / 256, 256>>>();
    }
    prep_w_kernel<<<(9 * CC * CC + 255) / 256, 256>>>(wgt);
    {
        dim3 g(WW / 32, CC / 32, HH), b(32, 8);
        prep_x_kernel<<<g, b>>>(x);
    }

    cudaFuncSetAttribute(conv_main, cudaFuncAttributeMaxDynamicSharedMemorySize, SMEM_BYTES);
    dim3 grid(WW / 64, HH / 2, 2);
    conv_main<<<grid, 256, SMEM_BYTES>>>(spa, chm, out);

    const int conv_elems = CC * HW;
    if (out_size >= conv_elems + 2 * CC) {
        chround_kernel<<<1, 256>>>(chm, out + conv_elems);
    }
}